// round 12
// baseline (speedup 1.0000x reference)
#include <cuda_runtime.h>
#include <cuda_fp16.h>
#include <cstdint>

// NeuralCRF log-partition backward DP, one CTA per batch (B=64), 128 threads.
// Tensor-core step: t = E * (t .* pre) via mma.sync.m16n8k16 (HMMA, f16 acc).
// E = exp(trans) preloaded ONCE as A-fragments (2 Mtiles x 8 Kchunks x 4 b32
// regs per lane). B columns are all identical (broadcast u), so b-frags are
// contiguous half2 LDS.32 from u_sm, and the D fragment holds each row's sum
// replicated across lanes: lane (g,t) of warp w owns row 32w+8t+g (bijection)
// and just selects its register -> HMUL by off-path pre -> STS.16.
// Shift schedule m is predetermined 2 executed steps ahead from broadcast t0
// (uniform off-path m-chain on all threads); pre = exp(em + Delta) computed
// a full iteration early. ONE __syncthreads per step; u/t0 double-buffered.
// Exact fp32 block logsumexp at the end.

#define TDIM 128

typedef unsigned int u32;

__device__ __forceinline__ void mma16816(u32& d0, u32& d1,
                                         u32 a0, u32 a1, u32 a2, u32 a3,
                                         u32 b0, u32 b1)
{
    asm volatile(
        "mma.sync.aligned.m16n8k16.row.col.f16.f16.f16.f16 "
        "{%0,%1}, {%2,%3,%4,%5}, {%6,%7}, {%0,%1};"
        : "+r"(d0), "+r"(d1)
        : "r"(a0), "r"(a1), "r"(a2), "r"(a3), "r"(b0), "r"(b1));
}

__device__ __forceinline__ u32 pack_e(float x, float y)
{
    __half2 h = __floats2half2_rn(__expf(x), __expf(y));
    u32 r;
    r = *reinterpret_cast<u32*>(&h);
    return r;
}

__global__ __launch_bounds__(TDIM, 1)
void crf_logz_kernel(const int* __restrict__ W,
                     const float* __restrict__ em,
                     const float* __restrict__ trans,
                     float* __restrict__ out,
                     int S)
{
    const int b    = blockIdx.x;
    const int tid  = threadIdx.x;
    const int wrp  = tid >> 5;
    const int ln   = tid & 31;
    const int g    = ln >> 2;              // fragment group id (0..7)
    const int tq   = ln & 3;               // thread-in-group  (0..3)
    const int row  = 32 * wrp + 8 * tq + g;  // the row this lane OWNS

    extern __shared__ int smem_dyn[];
    int* w_sm = smem_dyn;                  // S word ids
    __shared__ __align__(16) __half u_sm[2][TDIM];
    __shared__ float t0_sm[2];
    __shared__ float red_sm[8];

    // ---- A-fragments of E = exp(trans): [tile][k-chunk][reg] ----
    // For tile m (rows 32w+16m .. +15), chunk c (cols 16c .. 16c+15):
    //   a0: row (32w+16m+g),   cols 16c+2tq,   +1
    //   a1: row (32w+16m+g+8), cols 16c+2tq,   +1
    //   a2: row (32w+16m+g),   cols 16c+2tq+8, +9
    //   a3: row (32w+16m+g+8), cols 16c+2tq+8, +9
    u32 A[2][8][4];
#pragma unroll
    for (int m = 0; m < 2; ++m) {
        int ra = 32 * wrp + 16 * m + g;
#pragma unroll
        for (int c = 0; c < 8; ++c) {
            int j0 = 16 * c + 2 * tq;
            float2 q0 = *reinterpret_cast<const float2*>(trans + ra * TDIM + j0);
            float2 q1 = *reinterpret_cast<const float2*>(trans + (ra + 8) * TDIM + j0);
            float2 q2 = *reinterpret_cast<const float2*>(trans + ra * TDIM + j0 + 8);
            float2 q3 = *reinterpret_cast<const float2*>(trans + (ra + 8) * TDIM + j0 + 8);
            A[m][c][0] = pack_e(q0.x, q0.y);
            A[m][c][1] = pack_e(q1.x, q1.y);
            A[m][c][2] = pack_e(q2.x, q2.y);
            A[m][c][3] = pack_e(q3.x, q3.y);
        }
    }
    const float trans_bot = __ldg(trans + 1 * TDIM + row);  // trans[BOT=1,row]

    const float* emb = em + (size_t)b * (size_t)S * TDIM;
    const int*   Wb  = W  + (size_t)b * (size_t)S;

    for (int k = tid; k < S; k += TDIM) w_sm[k] = Wb[k];    // one-time

    // Raw state in HALF: t_h = exp(Beta_row - m_prev); Beta=0, m_{-1}=0 -> 1.
    __half t_h = __float2half_rn(1.0f);
    float m_prev = 0.0f, m_cur = 3.5f, m_nxt = 9.0f;        // shift schedule
    float dN = m_prev - m_cur;

    if (tid == 0) { t0_sm[0] = 1.0f; t0_sm[1] = 1.0f; }

    float eA = emb[(size_t)(S - 1) * TDIM + row];
    float eB = emb[(size_t)(S - 2) * TDIM + row];
    __half preA = __float2half_rn(__expf(eA + dN));

    int p = 0;
    __syncthreads();                 // covers w_sm

    int wA = w_sm[S - 1];
    int wB = w_sm[S - 2];

    for (int r = S - 1; r >= 1; --r) {
        int rp = r - 2;
        rp = rp < 0 ? 0 : rp;
        float eC = emb[(size_t)rp * TDIM + row];
        int   wC = w_sm[rp];

        if ((wA != 0) & (wA != 3)) {          // mask, uniform across block
            u_sm[p][row] = __hmul(t_h, preA); // ON-PATH: HMUL -> STS.16
            __syncthreads();                  // the ONLY barrier per step

            float T0 = t0_sm[p ^ 1];          // off-path broadcast

            // ---- tensor-core contraction: 4 chains (2 tiles x even/odd) --
            u32 dE0a = 0u, dE0b = 0u, dO0a = 0u, dO0b = 0u;
            u32 dE1a = 0u, dE1b = 0u, dO1a = 0u, dO1b = 0u;
            const __half* up = u_sm[p];
#pragma unroll
            for (int c = 0; c < 8; ++c) {
                u32 b0 = *reinterpret_cast<const u32*>(up + 16 * c + 2 * tq);
                u32 b1 = *reinterpret_cast<const u32*>(up + 16 * c + 2 * tq + 8);
                if (c & 1) {
                    mma16816(dO0a, dO0b, A[0][c][0], A[0][c][1], A[0][c][2], A[0][c][3], b0, b1);
                    mma16816(dO1a, dO1b, A[1][c][0], A[1][c][1], A[1][c][2], A[1][c][3], b0, b1);
                } else {
                    mma16816(dE0a, dE0b, A[0][c][0], A[0][c][1], A[0][c][2], A[0][c][3], b0, b1);
                    mma16816(dE1a, dE1b, A[1][c][0], A[1][c][1], A[1][c][2], A[1][c][3], b0, b1);
                }
            }
            // lane (g,tq) owns row 32w+8tq+g:
            //  tq=0 -> tile0 d0 (row g);    tq=1 -> tile0 d1 (row g+8)
            //  tq=2 -> tile1 d0 (row g+16); tq=3 -> tile1 d1 (row g+24)
            u32 sE = (tq == 0) ? dE0a : (tq == 1) ? dE0b
                    : (tq == 2) ? dE1a : dE1b;
            u32 sO = (tq == 0) ? dO0a : (tq == 1) ? dO0b
                    : (tq == 2) ? dO1a : dO1b;
            __half2 hE = *reinterpret_cast<__half2*>(&sE);
            __half2 hO = *reinterpret_cast<__half2*>(&sO);
            __half2 sum2 = __hadd2(hE, hO);
            t_h = __low2half(sum2);           // both halves identical

            if (tid == 0) t0_sm[p] = __half2float(t_h);  // off-path publish

            // ---- OFF-PATH uniform m-chain (fp32) ----
            float m_new = m_prev + __logf(T0) + 10.85f;
            m_prev = m_cur;
            m_cur  = m_nxt;
            m_nxt  = m_new;
            dN = m_prev - m_cur;
            p ^= 1;
        }

        __half preB = __float2half_rn(__expf(eB + dN));  // off-path

        eA = eB;  preA = preB;  wA = wB;
        eB = eC;  wB = wC;
    }

    // ---- logZ = lse_row( trans[BOT,row] + em[b,0,row] + m_last + log t ) --
    float f = trans_bot + eA + m_prev + __logf(__half2float(t_h));

    float mv = f;
#pragma unroll
    for (int o = 16; o > 0; o >>= 1)
        mv = fmaxf(mv, __shfl_xor_sync(0xffffffffu, mv, o));
    if ((tid & 31) == 0) red_sm[tid >> 5] = mv;
    __syncthreads();
    float mm = fmaxf(fmaxf(red_sm[0], red_sm[1]), fmaxf(red_sm[2], red_sm[3]));

    float s = __expf(f - mm);
#pragma unroll
    for (int o = 16; o > 0; o >>= 1)
        s += __shfl_xor_sync(0xffffffffu, s, o);
    if ((tid & 31) == 0) red_sm[4 + (tid >> 5)] = s;
    __syncthreads();

    if (tid == 0) {
        float tot = (red_sm[4] + red_sm[5]) + (red_sm[6] + red_sm[7]);
        out[b] = mm + __logf(tot);
    }
}

extern "C" void kernel_launch(void* const* d_in, const int* in_sizes, int n_in,
                              void* d_out, int out_size)
{
    const int*   W     = (const int*)d_in[0];
    const float* em    = (const float*)d_in[1];
    const float* trans = (const float*)d_in[2];
    float*       out   = (float*)d_out;

    const int B = out_size;            // 64
    const int S = in_sizes[0] / B;     // 1024

    crf_logz_kernel<<<B, TDIM, S * (int)sizeof(int)>>>(W, em, trans, out, S);
}

// round 13
// speedup vs baseline: 2.5374x; 2.5374x over previous
#include <cuda_runtime.h>
#include <cuda_fp16.h>

// NeuralCRF log-partition backward DP, one CTA per batch (B=64), 128 threads.
// All-fp16 serial spine (R10) + PRE-COMPACTED step list: a one-time parallel
// scan over the pad/eos mask builds the list of executed step rows, so the
// serial loop has NO conditional (no BSSY/BSYNC, no mask ops, no word
// rotation). Accumulators are initialized by first-touch HMUL2 (no zero-init).
// Per step: u_j = t_j * pre_j (HMUL, pre computed OFF-PATH one iteration
// early from the predetermined shift schedule), t_i = sum_j exp(trans_ij)*u_j
// via 64 HFMA2/HMUL2 into 8 rotating half2 accs, 3-level HADD2 tree + HADD.
// Shift schedule m set 2 executed steps ahead from broadcast t0; uniform
// off-path fp32 m-chain on all threads. ONE __syncthreads per step;
// u/t0 double-buffered by step parity. Exact fp32 block logsumexp at end.

#define TDIM 128

__global__ __launch_bounds__(TDIM, 1)
void crf_logz_kernel(const int* __restrict__ W,
                     const float* __restrict__ em,
                     const float* __restrict__ trans,
                     float* __restrict__ out,
                     int S)
{
    const int b = blockIdx.x;
    const int i = threadIdx.x;

    extern __shared__ int list_sm[];               // words, then step list
    __shared__ __align__(16) __half u_sm[2][TDIM];
    __shared__ float t0_sm[2];
    __shared__ float red_sm[8];
    __shared__ int wtot_sm[4];

    // ---- E row i = exp(trans[i,:]) as 64 half2 registers (one-time) ----
    __half2 e2[TDIM / 2];
    {
        const float4* trow = reinterpret_cast<const float4*>(trans + i * TDIM);
#pragma unroll
        for (int j4 = 0; j4 < TDIM / 4; ++j4) {
            float4 t4 = __ldg(trow + j4);
            e2[2 * j4 + 0] = __floats2half2_rn(__expf(t4.x), __expf(t4.y));
            e2[2 * j4 + 1] = __floats2half2_rn(__expf(t4.z), __expf(t4.w));
        }
    }
    const float trans_bot = __ldg(trans + 1 * TDIM + i);  // trans[BOT=1, i]

    const float* emb = em + (size_t)b * (size_t)S * TDIM;
    const int*   Wb  = W  + (size_t)b * (size_t)S;

    // ---- One-time: build compacted list of executed rows (descending r) --
    for (int k = i; k < S; k += TDIM) list_sm[k] = Wb[k];
    __syncthreads();

    int myr[8];
    int c = 0;
#pragma unroll
    for (int j = 0; j < 8; ++j) {
        int q = i * 8 + j;                 // q ascending -> r descending
        if (q < S - 1) {
            int r = S - 1 - q;
            int wv = list_sm[r];
            if ((wv != 0) & (wv != 3)) myr[c++] = r;
        }
    }
    // exclusive prefix of c over 128 threads
    int pr = c;
#pragma unroll
    for (int o = 1; o < 32; o <<= 1) {
        int v = __shfl_up_sync(0xffffffffu, pr, o);
        if ((i & 31) >= o) pr += v;
    }
    if ((i & 31) == 31) wtot_sm[i >> 5] = pr;
    __syncthreads();                       // also: all list_sm reads done
    int excl = pr - c;
    for (int ww = 0; ww < (i >> 5); ++ww) excl += wtot_sm[ww];
    const int n_exec = wtot_sm[0] + wtot_sm[1] + wtot_sm[2] + wtot_sm[3];
    for (int j = 0; j < c; ++j) list_sm[excl + j] = myr[j];  // overwrite words
    if (i == 0) { t0_sm[0] = 1.0f; t0_sm[1] = 1.0f; }
    __syncthreads();

    // ---- Serial DP over compacted steps ----
    __half t_h = __float2half_rn(1.0f);    // exp(Beta - m_prev), m_{-1}=0
    float m_prev = 0.0f, m_cur = 3.5f, m_nxt = 9.0f;
    float dN = m_prev - m_cur;

    int r0 = (n_exec > 0) ? list_sm[0] : 1;
    int r1 = (n_exec > 1) ? list_sm[1] : r0;
    float eA = emb[(size_t)r0 * TDIM + i];
    float eB = emb[(size_t)r1 * TDIM + i];
    __half preA = __float2half_rn(__expf(eA + dN));

#pragma unroll 2
    for (int k = 0; k < n_exec; ++k) {
        const int p = k & 1;
        // off-path: prefetch emission for step k+2
        int kk = (k + 2 < n_exec) ? (k + 2) : (n_exec - 1);
        float eC = emb[(size_t)list_sm[kk] * TDIM + i];

        u_sm[p][i] = __hmul(t_h, preA);    // ON-PATH: HMUL -> STS.16
        __syncthreads();                   // the ONLY barrier per step

        float T0 = t0_sm[p ^ 1];           // off-path broadcast

        __half2 acc[8];
        const uint4* u4p = reinterpret_cast<const uint4*>(u_sm[p]);
        {   // k-chunks 0,1: first-touch init (HMUL2, no zero-init)
            uint4 w0 = u4p[0];
            uint4 w1 = u4p[1];
            acc[0] = __hmul2(e2[0], *reinterpret_cast<__half2*>(&w0.x));
            acc[1] = __hmul2(e2[1], *reinterpret_cast<__half2*>(&w0.y));
            acc[2] = __hmul2(e2[2], *reinterpret_cast<__half2*>(&w0.z));
            acc[3] = __hmul2(e2[3], *reinterpret_cast<__half2*>(&w0.w));
            acc[4] = __hmul2(e2[4], *reinterpret_cast<__half2*>(&w1.x));
            acc[5] = __hmul2(e2[5], *reinterpret_cast<__half2*>(&w1.y));
            acc[6] = __hmul2(e2[6], *reinterpret_cast<__half2*>(&w1.z));
            acc[7] = __hmul2(e2[7], *reinterpret_cast<__half2*>(&w1.w));
        }
#pragma unroll
        for (int kq = 2; kq < 16; ++kq) {  // 14 x LDS.128 broadcast
            uint4 w = u4p[kq];
            acc[(4 * kq + 0) & 7] = __hfma2(e2[4 * kq + 0],
                *reinterpret_cast<__half2*>(&w.x), acc[(4 * kq + 0) & 7]);
            acc[(4 * kq + 1) & 7] = __hfma2(e2[4 * kq + 1],
                *reinterpret_cast<__half2*>(&w.y), acc[(4 * kq + 1) & 7]);
            acc[(4 * kq + 2) & 7] = __hfma2(e2[4 * kq + 2],
                *reinterpret_cast<__half2*>(&w.z), acc[(4 * kq + 2) & 7]);
            acc[(4 * kq + 3) & 7] = __hfma2(e2[4 * kq + 3],
                *reinterpret_cast<__half2*>(&w.w), acc[(4 * kq + 3) & 7]);
        }
#pragma unroll
        for (int j = 0; j < 4; ++j) acc[j] = __hadd2(acc[j], acc[j + 4]);
        acc[0] = __hadd2(acc[0], acc[2]);
        acc[1] = __hadd2(acc[1], acc[3]);
        acc[0] = __hadd2(acc[0], acc[1]);
        t_h = __hadd(__low2half(acc[0]), __high2half(acc[0]));

        if (i == 0) t0_sm[p] = __half2float(t_h);   // off-path publish

        // ---- OFF-PATH uniform m-chain (fp32) ----
        float m_new = m_prev + __logf(T0) + 10.85f;
        m_prev = m_cur;
        m_cur  = m_nxt;
        m_nxt  = m_new;
        dN = m_prev - m_cur;

        __half preB = __float2half_rn(__expf(eB + dN));  // off-path

        eA = eB;  preA = preB;
        eB = eC;
    }

    // ---- logZ = lse_i( trans[BOT,i] + em[b,0,i] + m_last + log t_i ) ----
    float e0 = emb[i];                      // emissions[b, 0, i]
    float f = trans_bot + e0 + m_prev + __logf(__half2float(t_h));

    float mv = f;
#pragma unroll
    for (int o = 16; o > 0; o >>= 1)
        mv = fmaxf(mv, __shfl_xor_sync(0xffffffffu, mv, o));
    if ((i & 31) == 0) red_sm[i >> 5] = mv;
    __syncthreads();
    float mm = fmaxf(fmaxf(red_sm[0], red_sm[1]), fmaxf(red_sm[2], red_sm[3]));

    float s = __expf(f - mm);
#pragma unroll
    for (int o = 16; o > 0; o >>= 1)
        s += __shfl_xor_sync(0xffffffffu, s, o);
    if ((i & 31) == 0) red_sm[4 + (i >> 5)] = s;
    __syncthreads();

    if (i == 0) {
        float tot = (red_sm[4] + red_sm[5]) + (red_sm[6] + red_sm[7]);
        out[b] = mm + __logf(tot);
    }
}

extern "C" void kernel_launch(void* const* d_in, const int* in_sizes, int n_in,
                              void* d_out, int out_size)
{
    const int*   W     = (const int*)d_in[0];
    const float* em    = (const float*)d_in[1];
    const float* trans = (const float*)d_in[2];
    float*       out   = (float*)d_out;

    const int B = out_size;            // 64
    const int S = in_sizes[0] / B;     // 1024

    crf_logz_kernel<<<B, TDIM, S * (int)sizeof(int)>>>(W, em, trans, out, S);
}

// round 14
// speedup vs baseline: 2.6196x; 1.0324x over previous
#include <cuda_runtime.h>
#include <cuda_fp16.h>

// NeuralCRF log-partition backward DP, one CTA per batch (B=64), 128 threads.
// All-fp16 serial spine + pre-compacted executed-step list (padded by 2 so
// the serial loop has no conditionals at all). Per step:
//   u_j = t_j * pre_j (HMUL; pre computed OFF-PATH one iteration early from
//   the predetermined shift schedule), t_i = sum_j exp(trans_ij) * u_j via
//   60 HFMA2 + 4 HMUL2 (first-touch init) into 4 rotating half2 accs,
//   2-level HADD2 tree + HADD fold.
// Shift schedule m set 2 executed steps ahead from broadcast t0; uniform
// off-path fp32 m-chain on all threads. ONE __syncthreads per step;
// u/t0 double-buffered by step parity. Exact fp32 block logsumexp at end.

#define TDIM 128

__global__ __launch_bounds__(TDIM, 1)
void crf_logz_kernel(const int* __restrict__ W,
                     const float* __restrict__ em,
                     const float* __restrict__ trans,
                     float* __restrict__ out,
                     int S)
{
    const int b = blockIdx.x;
    const int i = threadIdx.x;

    extern __shared__ int list_sm[];               // words, then step list
    __shared__ __align__(16) __half u_sm[2][TDIM];
    __shared__ float t0_sm[2];
    __shared__ float red_sm[8];
    __shared__ int wtot_sm[4];

    // ---- E row i = exp(trans[i,:]) as 64 half2 registers (one-time) ----
    __half2 e2[TDIM / 2];
    {
        const float4* trow = reinterpret_cast<const float4*>(trans + i * TDIM);
#pragma unroll
        for (int j4 = 0; j4 < TDIM / 4; ++j4) {
            float4 t4 = __ldg(trow + j4);
            e2[2 * j4 + 0] = __floats2half2_rn(__expf(t4.x), __expf(t4.y));
            e2[2 * j4 + 1] = __floats2half2_rn(__expf(t4.z), __expf(t4.w));
        }
    }
    const float trans_bot = __ldg(trans + 1 * TDIM + i);  // trans[BOT=1, i]

    const float* emb = em + (size_t)b * (size_t)S * TDIM;
    const int*   Wb  = W  + (size_t)b * (size_t)S;

    // ---- One-time: build compacted list of executed rows (descending r) --
    for (int k = i; k < S; k += TDIM) list_sm[k] = Wb[k];
    __syncthreads();

    int myr[8];
    int c = 0;
#pragma unroll
    for (int j = 0; j < 8; ++j) {
        int q = i * 8 + j;                 // q ascending -> r descending
        if (q < S - 1) {
            int r = S - 1 - q;
            int wv = list_sm[r];
            if ((wv != 0) & (wv != 3)) myr[c++] = r;
        }
    }
    // exclusive prefix of c over 128 threads
    int pr = c;
#pragma unroll
    for (int o = 1; o < 32; o <<= 1) {
        int v = __shfl_up_sync(0xffffffffu, pr, o);
        if ((i & 31) >= o) pr += v;
    }
    if ((i & 31) == 31) wtot_sm[i >> 5] = pr;
    __syncthreads();                       // also: all list_sm reads done
    int excl = pr - c;
    for (int ww = 0; ww < (i >> 5); ++ww) excl += wtot_sm[ww];
    const int n_exec = wtot_sm[0] + wtot_sm[1] + wtot_sm[2] + wtot_sm[3];
    for (int j = 0; j < c; ++j) list_sm[excl + j] = myr[j];  // overwrite words
    if (i == 0) {
        t0_sm[0] = 1.0f; t0_sm[1] = 1.0f;
        list_sm[n_exec]     = 0;           // pad: prefetch index always valid
        list_sm[n_exec + 1] = 0;
    }
    __syncthreads();

    // ---- Serial DP over compacted steps (no conditionals) ----
    __half t_h = __float2half_rn(1.0f);    // exp(Beta - m_prev), m_{-1}=0
    float m_prev = 0.0f, m_cur = 3.5f, m_nxt = 9.0f;
    float dN = m_prev - m_cur;

    float eA = emb[(size_t)list_sm[0] * TDIM + i];
    float eB = emb[(size_t)list_sm[1] * TDIM + i];
    __half preA = __float2half_rn(__expf(eA + dN));

#pragma unroll 2
    for (int k = 0; k < n_exec; ++k) {
        const int p = k & 1;
        float eC = emb[(size_t)list_sm[k + 2] * TDIM + i];  // padded: no min

        u_sm[p][i] = __hmul(t_h, preA);    // ON-PATH: HMUL -> STS.16
        __syncthreads();                   // the ONLY barrier per step

        __half2 acc[4];
        const uint4* u4p = reinterpret_cast<const uint4*>(u_sm[p]);
        {   // k-chunk 0: first-touch init (HMUL2, no zero-init)
            uint4 w0 = u4p[0];
            acc[0] = __hmul2(e2[0], *reinterpret_cast<__half2*>(&w0.x));
            acc[1] = __hmul2(e2[1], *reinterpret_cast<__half2*>(&w0.y));
            acc[2] = __hmul2(e2[2], *reinterpret_cast<__half2*>(&w0.z));
            acc[3] = __hmul2(e2[3], *reinterpret_cast<__half2*>(&w0.w));
        }
#pragma unroll
        for (int kq = 1; kq < 16; ++kq) {  // 15 x LDS.128 broadcast
            uint4 w = u4p[kq];
            acc[0] = __hfma2(e2[4 * kq + 0],
                *reinterpret_cast<__half2*>(&w.x), acc[0]);
            acc[1] = __hfma2(e2[4 * kq + 1],
                *reinterpret_cast<__half2*>(&w.y), acc[1]);
            acc[2] = __hfma2(e2[4 * kq + 2],
                *reinterpret_cast<__half2*>(&w.z), acc[2]);
            acc[3] = __hfma2(e2[4 * kq + 3],
                *reinterpret_cast<__half2*>(&w.w), acc[3]);
        }
        acc[0] = __hadd2(acc[0], acc[2]);
        acc[1] = __hadd2(acc[1], acc[3]);
        acc[0] = __hadd2(acc[0], acc[1]);
        t_h = __hadd(__low2half(acc[0]), __high2half(acc[0]));

        float T0 = t0_sm[p ^ 1];           // off-path broadcast (prev step)
        if (i == 0) t0_sm[p] = __half2float(t_h);   // off-path publish

        // ---- OFF-PATH uniform m-chain (fp32) ----
        float m_new = m_prev + __logf(T0) + 10.85f;
        m_prev = m_cur;
        m_cur  = m_nxt;
        m_nxt  = m_new;
        dN = m_prev - m_cur;

        __half preB = __float2half_rn(__expf(eB + dN));  // off-path

        eA = eB;  preA = preB;
        eB = eC;
    }

    // ---- logZ = lse_i( trans[BOT,i] + em[b,0,i] + m_last + log t_i ) ----
    float e0 = emb[i];                      // emissions[b, 0, i]
    float f = trans_bot + e0 + m_prev + __logf(__half2float(t_h));

    float mv = f;
#pragma unroll
    for (int o = 16; o > 0; o >>= 1)
        mv = fmaxf(mv, __shfl_xor_sync(0xffffffffu, mv, o));
    if ((i & 31) == 0) red_sm[i >> 5] = mv;
    __syncthreads();
    float mm = fmaxf(fmaxf(red_sm[0], red_sm[1]), fmaxf(red_sm[2], red_sm[3]));

    float s = __expf(f - mm);
#pragma unroll
    for (int o = 16; o > 0; o >>= 1)
        s += __shfl_xor_sync(0xffffffffu, s, o);
    if ((i & 31) == 0) red_sm[4 + (i >> 5)] = s;
    __syncthreads();

    if (i == 0) {
        float tot = (red_sm[4] + red_sm[5]) + (red_sm[6] + red_sm[7]);
        out[b] = mm + __logf(tot);
    }
}

extern "C" void kernel_launch(void* const* d_in, const int* in_sizes, int n_in,
                              void* d_out, int out_size)
{
    const int*   W     = (const int*)d_in[0];
    const float* em    = (const float*)d_in[1];
    const float* trans = (const float*)d_in[2];
    float*       out   = (float*)d_out;

    const int B = out_size;            // 64
    const int S = in_sizes[0] / B;     // 1024

    crf_logz_kernel<<<B, TDIM, (S + 2) * (int)sizeof(int)>>>(W, em, trans, out, S);
}

// round 15
// speedup vs baseline: 2.8620x; 1.0925x over previous
#include <cuda_runtime.h>
#include <cuda_fp16.h>

// NeuralCRF log-partition backward DP, one CTA per batch (B=64), 128 threads.
// All-fp16 serial spine + pre-compacted executed-step list stored as
// emission-row OFFSETS (r*TDIM) and padded by 2 -> the serial loop has no
// conditionals and minimal addressing. Per step:
//   u_j = t_j * pre_j (HMUL; pre computed OFF-PATH right after the barrier,
//   overlapping the FMA phase), t_i = sum_j exp(trans_ij) * u_j via
//   4 HMUL2 (first-touch) + 60 HFMA2 into 4 rotating half2 accs,
//   2-level HADD2 tree + HADD fold.
// Shift schedule m set 2 executed steps ahead from broadcast t0; uniform
// fp32 m-chain on all threads placed directly after the barrier so its MUFUs
// run under the HFMA2 phase. ONE __syncthreads per step; u/t0 double-buffered
// by step parity. Exact fp32 block logsumexp at the end.

#define TDIM 128

__global__ __launch_bounds__(TDIM, 1)
void crf_logz_kernel(const int* __restrict__ W,
                     const float* __restrict__ em,
                     const float* __restrict__ trans,
                     float* __restrict__ out,
                     int S)
{
    const int b = blockIdx.x;
    const int i = threadIdx.x;

    extern __shared__ int list_sm[];               // words, then offset list
    __shared__ __align__(16) __half u_sm[2][TDIM];
    __shared__ float t0_sm[2];
    __shared__ float red_sm[8];
    __shared__ int wtot_sm[4];

    // ---- E row i = exp(trans[i,:]) as 64 half2 registers (one-time) ----
    __half2 e2[TDIM / 2];
    {
        const float4* trow = reinterpret_cast<const float4*>(trans + i * TDIM);
#pragma unroll
        for (int j4 = 0; j4 < TDIM / 4; ++j4) {
            float4 t4 = __ldg(trow + j4);
            e2[2 * j4 + 0] = __floats2half2_rn(__expf(t4.x), __expf(t4.y));
            e2[2 * j4 + 1] = __floats2half2_rn(__expf(t4.z), __expf(t4.w));
        }
    }
    const float trans_bot = __ldg(trans + 1 * TDIM + i);  // trans[BOT=1, i]

    const float* emb  = em + (size_t)b * (size_t)S * TDIM;
    const float* embi = emb + i;                   // pre-biased by row i
    const int*   Wb   = W  + (size_t)b * (size_t)S;

    // ---- One-time: build compacted offset list (descending r) ----
    for (int k = i; k < S; k += TDIM) list_sm[k] = Wb[k];
    __syncthreads();

    int myo[8];
    int c = 0;
#pragma unroll
    for (int j = 0; j < 8; ++j) {
        int q = i * 8 + j;                 // q ascending -> r descending
        if (q < S - 1) {
            int r = S - 1 - q;
            int wv = list_sm[r];
            if ((wv != 0) & (wv != 3)) myo[c++] = r * TDIM;  // float offset
        }
    }
    int pr = c;
#pragma unroll
    for (int o = 1; o < 32; o <<= 1) {
        int v = __shfl_up_sync(0xffffffffu, pr, o);
        if ((i & 31) >= o) pr += v;
    }
    if ((i & 31) == 31) wtot_sm[i >> 5] = pr;
    __syncthreads();                       // also: all list_sm reads done
    int excl = pr - c;
    for (int ww = 0; ww < (i >> 5); ++ww) excl += wtot_sm[ww];
    const int n_exec = wtot_sm[0] + wtot_sm[1] + wtot_sm[2] + wtot_sm[3];
    for (int j = 0; j < c; ++j) list_sm[excl + j] = myo[j];  // overwrite words
    if (i == 0) {
        t0_sm[0] = 1.0f; t0_sm[1] = 1.0f;
        list_sm[n_exec]     = 0;           // pad: prefetch always valid
        list_sm[n_exec + 1] = 0;
    }
    __syncthreads();

    // ---- Serial DP over compacted steps (no conditionals) ----
    __half t_h = __float2half_rn(1.0f);    // exp(Beta - m_prev), m_{-1}=0
    float m_prev = 0.0f, m_cur = 3.5f, m_nxt = 9.0f;
    float dN = m_prev - m_cur;

    float eA = __ldg(embi + list_sm[0]);
    float eB = __ldg(embi + list_sm[1]);
    __half preA = __float2half_rn(__expf(eA + dN));

#pragma unroll 4
    for (int k = 0; k < n_exec; ++k) {
        const int p = k & 1;
        float eC = __ldg(embi + list_sm[k + 2]);   // distance-2 prefetch

        u_sm[p][i] = __hmul(t_h, preA);    // ON-PATH: HMUL -> STS.16
        __syncthreads();                   // the ONLY barrier per step

        // ---- OFF-PATH work FIRST (overlaps the FMA phase below) ----
        float T0 = t0_sm[p ^ 1];           // prev step's t0 (visible now)
        float m_new = m_prev + __logf(T0) + 10.85f;
        m_prev = m_cur;
        m_cur  = m_nxt;
        m_nxt  = m_new;
        dN = m_prev - m_cur;
        __half preB = __float2half_rn(__expf(eB + dN));

        // ---- FMA phase ----
        __half2 acc[4];
        const uint4* u4p = reinterpret_cast<const uint4*>(u_sm[p]);
        {   // k-chunk 0: first-touch init (HMUL2, no zero-init)
            uint4 w0 = u4p[0];
            acc[0] = __hmul2(e2[0], *reinterpret_cast<__half2*>(&w0.x));
            acc[1] = __hmul2(e2[1], *reinterpret_cast<__half2*>(&w0.y));
            acc[2] = __hmul2(e2[2], *reinterpret_cast<__half2*>(&w0.z));
            acc[3] = __hmul2(e2[3], *reinterpret_cast<__half2*>(&w0.w));
        }
#pragma unroll
        for (int kq = 1; kq < 16; ++kq) {  // 15 x LDS.128 broadcast
            uint4 w = u4p[kq];
            acc[0] = __hfma2(e2[4 * kq + 0],
                *reinterpret_cast<__half2*>(&w.x), acc[0]);
            acc[1] = __hfma2(e2[4 * kq + 1],
                *reinterpret_cast<__half2*>(&w.y), acc[1]);
            acc[2] = __hfma2(e2[4 * kq + 2],
                *reinterpret_cast<__half2*>(&w.z), acc[2]);
            acc[3] = __hfma2(e2[4 * kq + 3],
                *reinterpret_cast<__half2*>(&w.w), acc[3]);
        }
        acc[0] = __hadd2(acc[0], acc[2]);
        acc[1] = __hadd2(acc[1], acc[3]);
        acc[0] = __hadd2(acc[0], acc[1]);
        t_h = __hadd(__low2half(acc[0]), __high2half(acc[0]));

        if (i == 0) t0_sm[p] = __half2float(t_h);   // off-path publish

        eA = eB;  preA = preB;
        eB = eC;
    }

    // ---- logZ = lse_i( trans[BOT,i] + em[b,0,i] + m_last + log t_i ) ----
    float e0 = emb[i];                      // emissions[b, 0, i]
    float f = trans_bot + e0 + m_prev + __logf(__half2float(t_h));

    float mv = f;
#pragma unroll
    for (int o = 16; o > 0; o >>= 1)
        mv = fmaxf(mv, __shfl_xor_sync(0xffffffffu, mv, o));
    if ((i & 31) == 0) red_sm[i >> 5] = mv;
    __syncthreads();
    float mm = fmaxf(fmaxf(red_sm[0], red_sm[1]), fmaxf(red_sm[2], red_sm[3]));

    float s = __expf(f - mm);
#pragma unroll
    for (int o = 16; o > 0; o >>= 1)
        s += __shfl_xor_sync(0xffffffffu, s, o);
    if ((i & 31) == 0) red_sm[4 + (i >> 5)] = s;
    __syncthreads();

    if (i == 0) {
        float tot = (red_sm[4] + red_sm[5]) + (red_sm[6] + red_sm[7]);
        out[b] = mm + __logf(tot);
    }
}

extern "C" void kernel_launch(void* const* d_in, const int* in_sizes, int n_in,
                              void* d_out, int out_size)
{
    const int*   W     = (const int*)d_in[0];
    const float* em    = (const float*)d_in[1];
    const float* trans = (const float*)d_in[2];
    float*       out   = (float*)d_out;

    const int B = out_size;            // 64
    const int S = in_sizes[0] / B;     // 1024

    crf_logz_kernel<<<B, TDIM, (S + 2) * (int)sizeof(int)>>>(W, em, trans, out, S);
}